// round 1
// baseline (speedup 1.0000x reference)
#include <cuda_runtime.h>
#include <math.h>

// Problem constants
#define NN 32
#define CC 256
#define HH 56
#define WW 56
#define HW (HH*WW)
#define QSTEP 0.0078125f   // 1/128

// Scratch for conv1 output (quantized), static device allocation (allowed).
__device__ float g_t2[(size_t)NN * CC * HH * WW];

// quantize: round to nearest multiple of 1/128, ties -> upper (matches reference)
__device__ __forceinline__ float quantize1(float v) {
    float s = floorf(v * 128.0f);
    float a = s * QSTEP;
    float b = (s + 1.0f) * QSTEP;
    return (fabsf(v - a) < fabsf(v - b)) ? a : b;
}

// packed fp32x2 FMA: d = a*b + d  (elementwise on the two lanes)
__device__ __forceinline__ void ffma2(unsigned long long& d,
                                      unsigned long long a,
                                      unsigned long long b) {
    asm("fma.rn.f32x2 %0, %1, %2, %0;" : "+l"(d) : "l"(a), "l"(b));
}

__device__ __forceinline__ unsigned long long dup2(float v) {
    unsigned long long r;
    asm("mov.b64 %0, {%1, %2};" : "=l"(r) : "f"(v), "f"(v));
    return r;
}

__device__ __forceinline__ float2 unpk(unsigned long long v) {
    float lo, hi;
    asm("mov.b64 {%0, %1}, %2;" : "=f"(lo), "=f"(hi) : "l"(v));
    return make_float2(lo, hi);
}

// One fused binary-conv stage.
//   QIN     : apply quantize() to inputs while staging to smem (conv1)
//   HASRES  : add residual before BN in epilogue (conv2); else BN+clip+quantize (conv1)
// Block: 64 output channels (blockIdx.y) x 8x8 pixel tile (blockIdx.x in 7x7) x batch (blockIdx.z)
// 256 threads: ty = cout-group (16 x 4 channels), tx -> (pixel row 0..7, col group 0..1 of 4)
template <bool QIN, bool HASRES>
__global__ __launch_bounds__(256)
void bconv_kernel(const float* __restrict__ X,
                  const float* __restrict__ Wt,      // OIHW fp32 (sign taken here)
                  const float* __restrict__ gamma,
                  const float* __restrict__ beta,
                  const float* __restrict__ mean,
                  const float* __restrict__ var,
                  const float* __restrict__ Res,     // residual (conv2) or nullptr
                  float* __restrict__ Out)
{
    // weights as +-1, layout [cin16][tap9][cout64] so cout pairs are contiguous (LDS.64)
    __shared__ float ws[16 * 9 * 64];                 // 36864 B
    // input halo tile, row stride 12 for 16B-aligned float4 window loads
    __shared__ float si[16][10][12];                  // 7680 B

    const int tid = threadIdx.x;
    const int ty  = tid >> 4;        // 0..15 : cout group (4 channels)
    const int tx  = tid & 15;        // 0..15 : pixel group (4 pixels)
    const int pr  = tx >> 1;         // pixel row in tile 0..7
    const int cg  = tx & 1;          // pixel col group (4 cols)
    const int n   = blockIdx.z;
    const int cb  = blockIdx.y;      // cout block (x64)
    const int th  = blockIdx.x / 7;
    const int tw  = blockIdx.x % 7;
    const int h0  = th * 8, w0 = tw * 8;

    // acc[cp][px]: cp = cout pair (channels cb*64 + ty*4 + 2cp + {0,1}), px = pixel 0..3
    unsigned long long acc[2][4];
#pragma unroll
    for (int a = 0; a < 2; a++)
#pragma unroll
        for (int b = 0; b < 4; b++) acc[a][b] = 0ull;

    for (int ch = 0; ch < 16; ++ch) {
        __syncthreads();   // protect smem reuse from previous chunk

        // ---- stage weights: signs of Wt[cb*64 .. +63][ch*16 .. +15][3][3]
        {
            const float* wg = Wt + (size_t)(cb * 64) * (CC * 9) + (size_t)(ch * 16) * 9;
#pragma unroll
            for (int j = 0; j < 36; j++) {           // 36*256 = 9216 elements
                int lin = tid + j * 256;
                int o   = lin / 144;                 // cout within block
                int rr  = lin - o * 144;             // i*9 + tap
                float wv = wg[(size_t)o * (CC * 9) + rr];
                ws[rr * 64 + o] = (wv >= 0.0f) ? 1.0f : -1.0f;
            }
        }

        // ---- stage input halo tile (16 ch x 10 x 10), zero-padded, optional quantize
        {
            const float* xin = X + ((size_t)n * CC + ch * 16) * HW;
#pragma unroll
            for (int j = 0; j < 7; j++) {
                int lin = tid + j * 256;
                if (lin < 1600) {
                    int c  = lin / 100;
                    int rm = lin - c * 100;
                    int hy = rm / 10;
                    int hx = rm - hy * 10;
                    int y  = h0 - 1 + hy;
                    int x  = w0 - 1 + hx;
                    float v = 0.0f;
                    if ((unsigned)y < (unsigned)HH && (unsigned)x < (unsigned)WW)
                        v = xin[(size_t)c * HW + y * WW + x];
                    if (QIN) v = quantize1(v);
                    si[c][hy][hx] = v;
                }
            }
        }
        __syncthreads();

        // ---- mainloop: 16 cin x 9 taps, packed f32x2 FMAs
#pragma unroll 2
        for (int i = 0; i < 16; i++) {
#pragma unroll
            for (int dy = 0; dy < 3; dy++) {
                const float* rowp = &si[i][pr + dy][cg * 4];
                float4 a4 = *(const float4*)rowp;        // halo cols cg*4 .. +3
                float2 b2 = *(const float2*)(rowp + 4);  // halo cols cg*4+4 .. +5
                unsigned long long xd[6];
                xd[0] = dup2(a4.x); xd[1] = dup2(a4.y); xd[2] = dup2(a4.z);
                xd[3] = dup2(a4.w); xd[4] = dup2(b2.x); xd[5] = dup2(b2.y);
#pragma unroll
                for (int dx = 0; dx < 3; dx++) {
                    const unsigned long long* wrow =
                        (const unsigned long long*)&ws[(i * 9 + dy * 3 + dx) * 64 + ty * 4];
                    unsigned long long w0p = wrow[0];   // couts ty*4+0,1 (broadcast LDS)
                    unsigned long long w1p = wrow[1];   // couts ty*4+2,3
                    ffma2(acc[0][0], w0p, xd[dx + 0]);
                    ffma2(acc[0][1], w0p, xd[dx + 1]);
                    ffma2(acc[0][2], w0p, xd[dx + 2]);
                    ffma2(acc[0][3], w0p, xd[dx + 3]);
                    ffma2(acc[1][0], w1p, xd[dx + 0]);
                    ffma2(acc[1][1], w1p, xd[dx + 1]);
                    ffma2(acc[1][2], w1p, xd[dx + 2]);
                    ffma2(acc[1][3], w1p, xd[dx + 3]);
                }
            }
        }
    }

    // ---- fused epilogue
    const int y = h0 + pr;
#pragma unroll
    for (int cp = 0; cp < 2; cp++) {
        int oc = cb * 64 + ty * 4 + cp * 2;
        float iv0 = gamma[oc]     * rsqrtf(var[oc]     + 1e-5f);
        float iv1 = gamma[oc + 1] * rsqrtf(var[oc + 1] + 1e-5f);
        float ad0 = beta[oc]     - mean[oc]     * iv0;
        float ad1 = beta[oc + 1] - mean[oc + 1] * iv1;
#pragma unroll
        for (int px = 0; px < 4; px++) {
            int x = w0 + cg * 4 + px;
            float2 v = unpk(acc[cp][px]);
            size_t idx0 = ((size_t)n * CC + oc) * HW + (size_t)y * WW + x;
            if (HASRES) {
                // conv2: (conv + residual) -> BN2 -> hardtanh
                float r0 = fminf(fmaxf((v.x + Res[idx0])      * iv0 + ad0, -1.0f), 1.0f);
                float r1 = fminf(fmaxf((v.y + Res[idx0 + HW]) * iv1 + ad1, -1.0f), 1.0f);
                Out[idx0]      = r0;
                Out[idx0 + HW] = r1;
            } else {
                // conv1: BN1 -> hardtanh -> quantize
                float r0 = quantize1(fminf(fmaxf(v.x * iv0 + ad0, -1.0f), 1.0f));
                float r1 = quantize1(fminf(fmaxf(v.y * iv1 + ad1, -1.0f), 1.0f));
                Out[idx0]      = r0;
                Out[idx0 + HW] = r1;
            }
        }
    }
}

extern "C" void kernel_launch(void* const* d_in, const int* in_sizes, int n_in,
                              void* d_out, int out_size)
{
    const float* x  = (const float*)d_in[0];
    const float* w1 = (const float*)d_in[1];
    const float* w2 = (const float*)d_in[2];
    const float* g1 = (const float*)d_in[3];
    const float* b1 = (const float*)d_in[4];
    const float* m1 = (const float*)d_in[5];
    const float* v1 = (const float*)d_in[6];
    const float* g2 = (const float*)d_in[7];
    const float* b2 = (const float*)d_in[8];
    const float* m2 = (const float*)d_in[9];
    const float* v2 = (const float*)d_in[10];
    float* out = (float*)d_out;

    float* t2 = nullptr;
    cudaGetSymbolAddress((void**)&t2, g_t2);   // address query only; no allocation

    dim3 grid(49, 4, NN);   // 7x7 pixel tiles, 4 cout blocks, 32 batch
    dim3 block(256);

    // conv1: quantize(x) -> binconv(w1) -> BN1 -> hardtanh -> quantize -> g_t2
    bconv_kernel<true,  false><<<grid, block>>>(x,  w1, g1, b1, m1, v1, nullptr, t2);
    // conv2: binconv(w2) on g_t2 -> +residual(x) -> BN2 -> hardtanh -> out
    bconv_kernel<false, true ><<<grid, block>>>(t2, w2, g2, b2, m2, v2, x, out);
}

// round 15
// speedup vs baseline: 7.8563x; 7.8563x over previous
#include <cuda_runtime.h>
#include <cstdint>
#include <math.h>

#define NN 32
#define CC 256
#define HH 56
#define WW 56
#define HWP (HH*WW)          // 3136
#define KTOT 2304            // 256*9
#define NKB 72               // K chunks of 32 tf32
#define QSTEP 0.0078125f

// SMEM float-offsets (row stride 36 floats = 144B, 16B aligned, conflict-free frags)
#define SA 36
#define OF_A0 0
#define OF_A1 4608
#define OF_B0 9216
#define OF_B1 11520
#define OF_IV 13824
#define OF_AD 13952
#define SMEM_FLOATS 14080    // 56320 bytes

// Global scratch (static device allocations are allowed)
__device__ float g_xq[(size_t)NN * HWP * CC];   // quantized input, NHWC
__device__ float g_t2[(size_t)NN * HWP * CC];   // conv1 output, NHWC
__device__ float g_aw1[(size_t)CC * KTOT];      // signed w1, im2col K order
__device__ float g_aw2[(size_t)CC * KTOT];      // signed w2, im2col K order

// ---------------- helpers ----------------
__device__ __forceinline__ float quantize1(float v) {
    float s = floorf(v * 128.0f);
    float a = s * QSTEP, b = (s + 1.0f) * QSTEP;
    return (fabsf(v - a) < fabsf(v - b)) ? a : b;
}

__device__ __forceinline__ uint32_t smem_u32(const void* p) {
    uint32_t a;
    asm("{ .reg .u64 t; cvta.to.shared.u64 t, %1; cvt.u32.u64 %0, t; }" : "=r"(a) : "l"(p));
    return a;
}

__device__ __forceinline__ void cp_async16(uint32_t dst, const void* src, uint32_t srcsize) {
    asm volatile("cp.async.ca.shared.global [%0], [%1], 16, %2;"
                 :: "r"(dst), "l"(src), "r"(srcsize) : "memory");
}

__device__ __forceinline__ void cp_commit() {
    asm volatile("cp.async.commit_group;" ::: "memory");
}

__device__ __forceinline__ void cp_wait1() {
    asm volatile("cp.async.wait_group 1;" ::: "memory");
}

__device__ __forceinline__ void cp_wait0() {
    asm volatile("cp.async.wait_group 0;" ::: "memory");
}

// m16n8k8 tf32 mma: C(16x8,f32) += A(16x8,tf32 row) * B(8x8,tf32 col)
__device__ __forceinline__ void mma_tf32(float* c, const uint32_t* a, const uint32_t* b) {
    asm volatile(
        "mma.sync.aligned.m16n8k8.row.col.f32.tf32.tf32.f32 "
        "{%0,%1,%2,%3}, {%4,%5,%6,%7}, {%8,%9}, {%0,%1,%2,%3};"
        : "+f"(c[0]), "+f"(c[1]), "+f"(c[2]), "+f"(c[3])
        : "r"(a[0]), "r"(a[1]), "r"(a[2]), "r"(a[3]), "r"(b[0]), "r"(b[1]));
}

// ---------------- prep kernels ----------------
// NCHW -> NHWC with quantize, 32ch x 32px smem tiles
__global__ __launch_bounds__(256)
void prep_x_kernel(const float* __restrict__ X, float* __restrict__ Xq) {
    __shared__ float sm[32][33];
    const int pb = blockIdx.x, cbl = blockIdx.y, n = blockIdx.z;
    const int tid = threadIdx.x;
    const int a = tid >> 5, bl = tid & 31;
#pragma unroll
    for (int i = 0; i < 4; i++) {
        int c = a + i * 8;
        float v = X[((size_t)n * CC + cbl * 32 + c) * HWP + pb * 32 + bl];
        sm[c][bl] = quantize1(v);
    }
    __syncthreads();
#pragma unroll
    for (int i = 0; i < 4; i++) {
        int p = a + i * 8;
        Xq[((size_t)n * HWP + pb * 32 + p) * CC + cbl * 32 + bl] = sm[bl][p];
    }
}

// OIHW weights -> signed +-1, K ordered as [cib(8)][tap(9)][ci(32)]
__global__ __launch_bounds__(256)
void prep_w_kernel(const float* __restrict__ W, float* __restrict__ A) {
    int idx = blockIdx.x * 256 + threadIdx.x;
    if (idx >= CC * KTOT) return;
    int cout = idx / KTOT, r = idx - cout * KTOT;
    int cin = r / 9, tap = r - cin * 9;
    float w = W[idx];
    A[(size_t)cout * KTOT + (cin >> 5) * 288 + tap * 32 + (cin & 31)] =
        (w >= 0.0f) ? 1.0f : -1.0f;
}

// ---------------- mma.sync implicit-GEMM conv ----------------
// CTA: 128 couts (blockIdx.y) x 64 pixels (8x8 tile, blockIdx.x) x batch (blockIdx.z)
// 8 warps: wm = wid&3 (M quarter, 32 couts), wn = wid>>2 (N half, 32 pixels)
template <bool HASRES>
__global__ __launch_bounds__(256)
void conv_mma(const float* __restrict__ Bsrc,   // NHWC input
              const float* __restrict__ Aw,     // signed weights [256][2304]
              const float* __restrict__ gamma, const float* __restrict__ beta,
              const float* __restrict__ mean,  const float* __restrict__ var,
              const float* __restrict__ Res,    // NCHW residual (conv2)
              float* __restrict__ Out)          // conv1: NHWC, conv2: NCHW
{
    extern __shared__ float sm[];
    const uint32_t sbase = smem_u32(sm);
    const int tid = threadIdx.x;
    const int wid = tid >> 5, lane = tid & 31;
    const int g = lane >> 2, tc = lane & 3;
    const int wm = wid & 3, wn = wid >> 2;
    const int cb = blockIdx.y;
    const int n  = blockIdx.z;
    const int y0 = (blockIdx.x / 7) * 8, x0 = (blockIdx.x % 7) * 8;

    const float* awBase = Aw + (size_t)(cb * 128) * KTOT;
    const float* bBase  = Bsrc + (size_t)n * HWP * CC;

    float acc[2][4][4];
#pragma unroll
    for (int i = 0; i < 2; i++)
#pragma unroll
        for (int j = 0; j < 4; j++)
#pragma unroll
            for (int k = 0; k < 4; k++) acc[i][j][k] = 0.0f;

    // B source coords per thread (fixed across chunks except tap shift)
    const int pA_o = tid >> 3, pA_v = tid & 7;          // A: row o (+32 rows per j)
    const int pB_p = tid >> 3, pB_v = tid & 7;          // B: pixel p, vec v (j adds 32 pixels)

    // ---- stage chunk kb into buffer ofs
    auto stage = [&](int kb, uint32_t ofA, uint32_t ofB) {
        const float* srcA = awBase + kb * 32;
#pragma unroll
        for (int j = 0; j < 4; j++) {
            int o = pA_o + j * 32;
            cp_async16(sbase + (ofA + o * SA + pA_v * 4) * 4,
                       srcA + (size_t)o * KTOT + pA_v * 4, 16);
        }
        const int cib = kb / 9, tap = kb - cib * 9;
        const int dy = tap / 3 - 1, dx = tap % 3 - 1;
        const float* srcB = bBase + cib * 32;
#pragma unroll
        for (int j = 0; j < 2; j++) {
            int p = pB_p + j * 32;
            int py = p >> 3, px = p & 7;
            int y = y0 + py + dy, x = x0 + px + dx;
            bool inb = ((unsigned)y < (unsigned)HH) && ((unsigned)x < (unsigned)WW);
            const float* src = inb ? (srcB + ((size_t)y * WW + x) * CC + pB_v * 4) : srcB;
            cp_async16(sbase + (ofB + p * SA + pB_v * 4) * 4, src, inb ? 16u : 0u);
        }
        cp_commit();
    };

    stage(0, OF_A0, OF_B0);

    for (int kb = 0; kb < NKB; ++kb) {
        const int b = kb & 1;
        if (kb + 1 < NKB) {
            stage(kb + 1, b ? OF_A0 : OF_A1, b ? OF_B0 : OF_B1);
            cp_wait1();
        } else {
            cp_wait0();
        }
        __syncthreads();

        const float* As = sm + (b ? OF_A1 : OF_A0);
        const float* Bs = sm + (b ? OF_B1 : OF_B0);
        const uint32_t* Au = (const uint32_t*)As;
        const uint32_t* Bu = (const uint32_t*)Bs;

#pragma unroll
        for (int ks = 0; ks < 32; ks += 8) {
            uint32_t af[2][4];
#pragma unroll
            for (int mt = 0; mt < 2; mt++) {
                int m0 = wm * 32 + mt * 16;
                af[mt][0] = Au[(m0 + g) * SA + ks + tc];
                af[mt][1] = Au[(m0 + g + 8) * SA + ks + tc];
                af[mt][2] = Au[(m0 + g) * SA + ks + tc + 4];
                af[mt][3] = Au[(m0 + g + 8) * SA + ks + tc + 4];
            }
            uint32_t bf[4][2];
#pragma unroll
            for (int nt = 0; nt < 4; nt++) {
                int n0 = wn * 32 + nt * 8;
                bf[nt][0] = Bu[(n0 + g) * SA + ks + tc];
                bf[nt][1] = Bu[(n0 + g) * SA + ks + tc + 4];
            }
#pragma unroll
            for (int mt = 0; mt < 2; mt++)
#pragma unroll
                for (int nt = 0; nt < 4; nt++)
                    mma_tf32(acc[mt][nt], af[mt], bf[nt]);
        }
        __syncthreads();
    }

    // ---- BN constants into smem
    if (tid < 128) {
        int oc = cb * 128 + tid;
        float iv = gamma[oc] * rsqrtf(var[oc] + 1e-5f);
        sm[OF_IV + tid] = iv;
        sm[OF_AD + tid] = beta[oc] - mean[oc] * iv;
    }
    __syncthreads();

    // ---- fused epilogue
#pragma unroll
    for (int mt = 0; mt < 2; mt++) {
#pragma unroll
        for (int h = 0; h < 2; h++) {
            const int r = wm * 32 + mt * 16 + h * 8 + g;     // cout within tile
            const int oc = cb * 128 + r;
            const float iv = sm[OF_IV + r];
            const float ad = sm[OF_AD + r];
            if (HASRES) {
                const size_t base = ((size_t)n * CC + oc) * HWP;
#pragma unroll
                for (int nt = 0; nt < 4; nt++) {
#pragma unroll
                    for (int e = 0; e < 2; e++) {
                        int col = wn * 32 + nt * 8 + 2 * tc + e;
                        int py = col >> 3, px = col & 7;
                        size_t idx = base + (size_t)(y0 + py) * WW + (x0 + px);
                        float v = (acc[mt][nt][2 * h + e] + Res[idx]) * iv + ad;
                        Out[idx] = fminf(fmaxf(v, -1.0f), 1.0f);
                    }
                }
            } else {
                const size_t base = (size_t)n * HWP * CC + oc;
#pragma unroll
                for (int nt = 0; nt < 4; nt++) {
#pragma unroll
                    for (int e = 0; e < 2; e++) {
                        int col = wn * 32 + nt * 8 + 2 * tc + e;
                        int py = col >> 3, px = col & 7;
                        float v = acc[mt][nt][2 * h + e] * iv + ad;
                        v = quantize1(fminf(fmaxf(v, -1.0f), 1.0f));
                        Out[base + ((size_t)(y0 + py) * WW + (x0 + px)) * CC] = v;
                    }
                }
            }
        }
    }
}

// ---------------- launch ----------------
extern "C" void kernel_launch(void* const* d_in, const int* in_sizes, int n_in,
                              void* d_out, int out_size)
{
    const float* x  = (const float*)d_in[0];
    const float* w1 = (const float*)d_in[1];
    const float* w2 = (const float*)d_in[2];
    const float* g1 = (const float*)d_in[3];
    const float* b1 = (const float*)d_in[4];
    const float* m1 = (const float*)d_in[5];
    const float* v1 = (const float*)d_in[6];
    const float* g2 = (const float*)d_in[7];
    const float* b2 = (const float*)d_in[8];
    const float* m2 = (const float*)d_in[9];
    const float* v2 = (const float*)d_in[10];
    float* out = (float*)d_out;

    float *xq, *t2, *aw1, *aw2;
    cudaGetSymbolAddress((void**)&xq,  g_xq);
    cudaGetSymbolAddress((void**)&t2,  g_t2);
    cudaGetSymbolAddress((void**)&aw1, g_aw1);
    cudaGetSymbolAddress((void**)&aw2, g_aw2);

    const int SMEM_BYTES = SMEM_FLOATS * 4;   // 56320
    cudaFuncSetAttribute(conv_mma<false>, cudaFuncAttributeMaxDynamicSharedMemorySize, SMEM_BYTES);
    cudaFuncSetAttribute(conv_mma<true>,  cudaFuncAttributeMaxDynamicSharedMemorySize, SMEM_BYTES);

    prep_x_kernel<<<dim3(98, 8, NN), 256>>>(x, xq);
    const int wn = CC * KTOT;
    prep_w_kernel<<<(wn + 255) / 256, 256>>>(w1, aw1);
    prep_w_kernel<<<(wn + 255) / 256, 256>>>(w2, aw2);

    dim3 grid(49, 2, NN);
    // conv1: quantized x (NHWC) -> binconv -> BN1 -> hardtanh -> quantize -> t2 (NHWC)
    conv_mma<false><<<grid, 256, SMEM_BYTES>>>(xq, aw1, g1, b1, m1, v1, nullptr, t2);
    // conv2: t2 (NHWC) -> binconv -> +residual(x NCHW) -> BN2 -> hardtanh -> out (NCHW)
    conv_mma<true><<<grid, 256, SMEM_BYTES>>>(t2, aw2, g2, b2, m2, v2, x, out);
}